// round 5
// baseline (speedup 1.0000x reference)
#include <cuda_runtime.h>

#define B_ 16
#define L_ 256
#define W_ 4
#define N_ 259          // L + W - 1
#define H_ 128
#define EPS_ 1e-6f
#define BN_ (B_ * N_)   // 4144

// Scratch (no allocations allowed). Zero-initialized at module load; slots that
// are never written stay 0 forever (every replay writes the same live slots),
// so summing all 5 slots is always correct and deterministic.
__device__ float g_norm[2 * BN_];        // [x1 rows | x2 rows]
__device__ float g_p1[16 * 5 * 320];     // x1_a partials: [b][slot][j]
__device__ float g_p2[16 * 5 * 320];     // x2_a partials: [b][slot][i]

// att = 1/(1+sqrt(d2)) = r/(1+r) with r = rsqrt(d2). Exact, 2 MUFU, no fixup.
__device__ __forceinline__ float att_of_d2(float d2) {
    float r = rsqrtf(d2);
    return __fdividef(r, 1.0f + r);
}

// ---------------------------------------------------------------------------
// 1) Row norms: one warp per (tensor, b, n) row of 128 floats.
// ---------------------------------------------------------------------------
__global__ void norms_kernel(const float* __restrict__ x1,
                             const float* __restrict__ x2) {
    int gt   = blockIdx.x * blockDim.x + threadIdx.x;
    int warp = gt >> 5;
    int lane = gt & 31;
    if (warp >= 2 * BN_) return;
    const float* x = (warp < BN_) ? x1 : x2;
    int row = (warp < BN_) ? warp : warp - BN_;
    float4 v = reinterpret_cast<const float4*>(x + (size_t)row * H_)[lane];
    float s = v.x * v.x + v.y * v.y + v.z * v.z + v.w * v.w;
#pragma unroll
    for (int o = 16; o > 0; o >>= 1) s += __shfl_xor_sync(0xffffffffu, s, o);
    if (lane == 0) g_norm[warp] = s;
}

// ---------------------------------------------------------------------------
// 2a) Main attention tiles: grid (16,16) = (tile, b). 64x64 tile over
//     [0,256)^2 with NO bounds checks. Emits both marginals.
//     Partial slots: p1 slots 0..3 (by it), q<256. p2 slots 0..3 (by jt), q<256.
// ---------------------------------------------------------------------------
__global__ void __launch_bounds__(256) attn_main(const float* __restrict__ x1,
                                                 const float* __restrict__ x2) {
    __shared__ float As[64][68];
    __shared__ float Bs[64][68];

    int b = blockIdx.y;
    int tid = threadIdx.x;
    const float* Ag = x2 + (size_t)b * N_ * H_;   // rows i
    const float* Bg = x1 + (size_t)b * N_ * H_;   // rows j
    const float* nA = g_norm + BN_ + b * N_;      // x2 norms
    const float* nB = g_norm + b * N_;            // x1 norms

    int it = blockIdx.x >> 2;
    int jt = blockIdx.x & 3;
    int tx = tid & 15;              // j group
    int ty = tid >> 4;              // i group
    int i0 = it * 64;
    int j0 = jt * 64;

    float acc[4][4];
#pragma unroll
    for (int r = 0; r < 4; r++)
#pragma unroll
        for (int c = 0; c < 4; c++) acc[r][c] = 0.0f;

    for (int hc = 0; hc < H_; hc += 64) {
        __syncthreads();
        int rot = tid & 3;
#pragma unroll
        for (int i = tid; i < 1024; i += 256) {
            int r  = i >> 4;
            int c4 = i & 15;
            float4 v = *reinterpret_cast<const float4*>(
                Ag + (size_t)(i0 + r) * H_ + hc + c4 * 4);
            float vv[4] = {v.x, v.y, v.z, v.w};
#pragma unroll
            for (int jj = 0; jj < 4; jj++) {
                int j = (jj + rot) & 3;
                As[c4 * 4 + j][r] = vv[j];
            }
        }
#pragma unroll
        for (int i = tid; i < 1024; i += 256) {
            int r  = i >> 4;
            int c4 = i & 15;
            float4 v = *reinterpret_cast<const float4*>(
                Bg + (size_t)(j0 + r) * H_ + hc + c4 * 4);
            float vv[4] = {v.x, v.y, v.z, v.w};
#pragma unroll
            for (int jj = 0; jj < 4; jj++) {
                int j = (jj + rot) & 3;
                Bs[c4 * 4 + j][r] = vv[j];
            }
        }
        __syncthreads();

#pragma unroll 16
        for (int h = 0; h < 64; h++) {
            float4 iv = *reinterpret_cast<const float4*>(&As[h][ty * 4]);
            float4 jv = *reinterpret_cast<const float4*>(&Bs[h][tx * 4]);
            acc[0][0] = fmaf(iv.x, jv.x, acc[0][0]);
            acc[0][1] = fmaf(iv.x, jv.y, acc[0][1]);
            acc[0][2] = fmaf(iv.x, jv.z, acc[0][2]);
            acc[0][3] = fmaf(iv.x, jv.w, acc[0][3]);
            acc[1][0] = fmaf(iv.y, jv.x, acc[1][0]);
            acc[1][1] = fmaf(iv.y, jv.y, acc[1][1]);
            acc[1][2] = fmaf(iv.y, jv.z, acc[1][2]);
            acc[1][3] = fmaf(iv.y, jv.w, acc[1][3]);
            acc[2][0] = fmaf(iv.z, jv.x, acc[2][0]);
            acc[2][1] = fmaf(iv.z, jv.y, acc[2][1]);
            acc[2][2] = fmaf(iv.z, jv.z, acc[2][2]);
            acc[2][3] = fmaf(iv.z, jv.w, acc[2][3]);
            acc[3][0] = fmaf(iv.w, jv.x, acc[3][0]);
            acc[3][1] = fmaf(iv.w, jv.y, acc[3][1]);
            acc[3][2] = fmaf(iv.w, jv.z, acc[3][2]);
            acc[3][3] = fmaf(iv.w, jv.w, acc[3][3]);
        }
    }

    // Epilogue: att + both marginals (no bounds checks).
    float nb[4];
#pragma unroll
    for (int c = 0; c < 4; c++) nb[c] = nB[j0 + tx * 4 + c];
    float jp[4] = {0.f, 0.f, 0.f, 0.f};
#pragma unroll
    for (int r = 0; r < 4; r++) {
        int i = i0 + ty * 4 + r;
        float na = nA[i];
        float is = 0.0f;
#pragma unroll
        for (int c = 0; c < 4; c++) {
            float d2  = fmaxf(na + nb[c] - 2.0f * acc[r][c], 0.0f) + EPS_;
            float att = att_of_d2(d2);
            is += att;
            jp[c] += att;
        }
#pragma unroll
        for (int o = 1; o < 16; o <<= 1)
            is += __shfl_xor_sync(0xffffffffu, is, o);
        if (tx == 0)
            g_p2[(b * 5 + jt) * 320 + i] = is;
    }
    __syncthreads();
    float* red = &As[0][0];
    *reinterpret_cast<float4*>(red + ty * 64 + tx * 4) =
        make_float4(jp[0], jp[1], jp[2], jp[3]);
    __syncthreads();
    if (tid < 64) {
        float s = 0.0f;
#pragma unroll
        for (int t = 0; t < 16; t++) s += red[t * 64 + tid];
        g_p1[(b * 5 + it) * 320 + j0 + tid] = s;
    }
}

// ---------------------------------------------------------------------------
// 2b) Strip kernel (own launch -> no register coupling with attn_main).
//     Phase A: i in [256,259) x all j -> p1 slot4 (all j), p2 slot4 (i>=256).
//     Phase B: j in [256,259) x i<256 -> p2 slot4 (i<256), p1 slot0 (j>=256).
// ---------------------------------------------------------------------------
__global__ void __launch_bounds__(256) attn_strip(const float* __restrict__ x1,
                                                  const float* __restrict__ x2) {
    __shared__ float SR[3][128];
    __shared__ float Red[3][256];

    int b = blockIdx.x;
    int tid = threadIdx.x;
    const float* Ag = x2 + (size_t)b * N_ * H_;   // rows i
    const float* Bg = x1 + (size_t)b * N_ * H_;   // rows j
    const float* nA = g_norm + BN_ + b * N_;
    const float* nB = g_norm + b * N_;

    // Phase A: i = 256..258 (x2 rows) vs ALL j in [0,259).
    for (int idx = tid; idx < 384; idx += 256)
        SR[idx >> 7][idx & 127] = Ag[(size_t)(256 + (idx >> 7)) * H_ + (idx & 127)];
    float na0 = nA[256], na1 = nA[257], na2 = nA[258];
    __syncthreads();

    float row0 = 0.f, row1 = 0.f, row2 = 0.f;
    for (int j = tid; j < N_; j += 256) {
        const float4* xr = reinterpret_cast<const float4*>(Bg + (size_t)j * H_);
        float d0 = 0.f, d1 = 0.f, d2d = 0.f;
#pragma unroll
        for (int q = 0; q < 32; q++) {
            float4 v = xr[q];
            const float* s0 = &SR[0][q * 4];
            const float* s1 = &SR[1][q * 4];
            const float* s2 = &SR[2][q * 4];
            d0 = fmaf(v.x, s0[0], d0); d0 = fmaf(v.y, s0[1], d0);
            d0 = fmaf(v.z, s0[2], d0); d0 = fmaf(v.w, s0[3], d0);
            d1 = fmaf(v.x, s1[0], d1); d1 = fmaf(v.y, s1[1], d1);
            d1 = fmaf(v.z, s1[2], d1); d1 = fmaf(v.w, s1[3], d1);
            d2d = fmaf(v.x, s2[0], d2d); d2d = fmaf(v.y, s2[1], d2d);
            d2d = fmaf(v.z, s2[2], d2d); d2d = fmaf(v.w, s2[3], d2d);
        }
        float nbj = nB[j];
        float a0 = att_of_d2(fmaxf(na0 + nbj - 2.f * d0, 0.f) + EPS_);
        float a1 = att_of_d2(fmaxf(na1 + nbj - 2.f * d1, 0.f) + EPS_);
        float a2 = att_of_d2(fmaxf(na2 + nbj - 2.f * d2d, 0.f) + EPS_);
        g_p1[(b * 5 + 4) * 320 + j] = a0 + a1 + a2;
        row0 += a0; row1 += a1; row2 += a2;
    }
    Red[0][tid] = row0; Red[1][tid] = row1; Red[2][tid] = row2;
    __syncthreads();
    if (tid < 96) {
        int r = tid >> 5, lane = tid & 31;
        float s = 0.f;
        for (int k = lane; k < 256; k += 32) s += Red[r][k];
#pragma unroll
        for (int o = 16; o > 0; o >>= 1) s += __shfl_xor_sync(0xffffffffu, s, o);
        if (lane == 0)
            g_p2[(b * 5 + 4) * 320 + 256 + r] = s;
    }
    __syncthreads();

    // Phase B: j = 256..258 (x1 rows) vs i in [0,256).
    for (int idx = tid; idx < 384; idx += 256)
        SR[idx >> 7][idx & 127] = Bg[(size_t)(256 + (idx >> 7)) * H_ + (idx & 127)];
    float nb0 = nB[256], nb1 = nB[257], nb2 = nB[258];
    __syncthreads();

    {
        int i = tid;   // exactly 256 i's
        const float4* xr = reinterpret_cast<const float4*>(Ag + (size_t)i * H_);
        float d0 = 0.f, d1 = 0.f, d2d = 0.f;
#pragma unroll
        for (int q = 0; q < 32; q++) {
            float4 v = xr[q];
            const float* s0 = &SR[0][q * 4];
            const float* s1 = &SR[1][q * 4];
            const float* s2 = &SR[2][q * 4];
            d0 = fmaf(v.x, s0[0], d0); d0 = fmaf(v.y, s0[1], d0);
            d0 = fmaf(v.z, s0[2], d0); d0 = fmaf(v.w, s0[3], d0);
            d1 = fmaf(v.x, s1[0], d1); d1 = fmaf(v.y, s1[1], d1);
            d1 = fmaf(v.z, s1[2], d1); d1 = fmaf(v.w, s1[3], d1);
            d2d = fmaf(v.x, s2[0], d2d); d2d = fmaf(v.y, s2[1], d2d);
            d2d = fmaf(v.z, s2[2], d2d); d2d = fmaf(v.w, s2[3], d2d);
        }
        float nai = nA[i];
        float a0 = att_of_d2(fmaxf(nai + nb0 - 2.f * d0, 0.f) + EPS_);
        float a1 = att_of_d2(fmaxf(nai + nb1 - 2.f * d1, 0.f) + EPS_);
        float a2 = att_of_d2(fmaxf(nai + nb2 - 2.f * d2d, 0.f) + EPS_);
        g_p2[(b * 5 + 4) * 320 + i] = a0 + a1 + a2;
        Red[0][tid] = a0; Red[1][tid] = a1; Red[2][tid] = a2;
    }
    __syncthreads();
    if (tid < 96) {
        int r = tid >> 5, lane = tid & 31;
        float s = 0.f;
        for (int k = lane; k < 256; k += 32) s += Red[r][k];
#pragma unroll
        for (int o = 16; o > 0; o >>= 1) s += __shfl_xor_sync(0xffffffffu, s, o);
        if (lane == 0)
            g_p1[(b * 5 + 0) * 320 + 256 + r] = s;
    }
}

// ---------------------------------------------------------------------------
// 3) Windowed weighted-sum. 1 float4 output per thread; inlines the 5-slot
//    partial reduction (warp-uniform loads: all lanes in a warp share l).
// ---------------------------------------------------------------------------
__global__ void wp_kernel(const float* __restrict__ x1,
                          const float* __restrict__ x2,
                          float* __restrict__ out) {
    int i = blockIdx.x * blockDim.x + threadIdx.x;   // (w,b,l,h4)
    if (i >= 2 * B_ * L_ * 32) return;
    int h4 = i & 31;
    int l  = (i >> 5) & 255;
    int b  = (i >> 13) & 15;
    int w  = i >> 17;
    const float* x = (w ? x2 : x1) + (size_t)b * N_ * H_ + h4 * 4;
    const float* p = (w ? g_p2 : g_p1) + b * 5 * 320;

    float4 o = make_float4(0.f, 0.f, 0.f, 0.f);
#pragma unroll
    for (int k = 0; k < W_; k++) {
        int q = l + k;
        float wg = 0.0f;
#pragma unroll
        for (int t = 0; t < 5; t++) wg += __ldg(p + t * 320 + q);
        float4 v = *reinterpret_cast<const float4*>(x + (size_t)q * H_);
        o.x = fmaf(v.x, wg, o.x);
        o.y = fmaf(v.y, wg, o.y);
        o.z = fmaf(v.z, wg, o.z);
        o.w = fmaf(v.w, wg, o.w);
    }
    reinterpret_cast<float4*>(out)[i] = o;
}

// ---------------------------------------------------------------------------
extern "C" void kernel_launch(void* const* d_in, const int* in_sizes, int n_in,
                              void* d_out, int out_size) {
    const float* x1 = (const float*)d_in[0];
    const float* x2 = (const float*)d_in[1];
    float* out = (float*)d_out;

    norms_kernel<<<(2 * BN_ * 32 + 255) / 256, 256>>>(x1, x2);

    dim3 grid_main(16, 16);
    attn_main<<<grid_main, 256>>>(x1, x2);

    attn_strip<<<16, 256>>>(x1, x2);

    wp_kernel<<<(2 * B_ * L_ * 32 + 255) / 256, 256>>>(x1, x2, out);
}

// round 6
// speedup vs baseline: 2.1082x; 2.1082x over previous
#include <cuda_runtime.h>

#define B_ 16
#define L_ 256
#define W_ 4
#define N_ 259          // L + W - 1
#define H_ 128
#define EPS_ 1e-6f
#define BN_ (B_ * N_)   // 4144

// Scratch (no allocations allowed).
__device__ float g_norm[2 * BN_];        // [x1 rows | x2 rows]
__device__ float g_p1[16 * 5 * 320];     // x1_a partials: [b][it][j padded]
__device__ float g_p2[16 * 5 * 320];     // x2_a partials: [b][jt][i padded]
__device__ float g_asum[2 * BN_];        // [x1_a | x2_a]

// att = 1/(1+sqrt(d2)) = r/(1+r), r = rsqrt(d2). Exact identity; one MUFU.RSQ
// plus one fast reciprocal — avoids the IEEE sqrtf fixup sequence entirely.
__device__ __forceinline__ float att_of_d2(float d2) {
    float r = rsqrtf(d2);
    return __fdividef(r, 1.0f + r);
}

// ---------------------------------------------------------------------------
// 1) Row norms: one warp per (tensor, b, n) row of 128 floats.
// ---------------------------------------------------------------------------
__global__ void norms_kernel(const float* __restrict__ x1,
                             const float* __restrict__ x2) {
    int gt   = blockIdx.x * blockDim.x + threadIdx.x;
    int warp = gt >> 5;
    int lane = gt & 31;
    if (warp >= 2 * BN_) return;
    const float* x = (warp < BN_) ? x1 : x2;
    int row = (warp < BN_) ? warp : warp - BN_;
    float4 v = reinterpret_cast<const float4*>(x + (size_t)row * H_)[lane];
    float s = v.x * v.x + v.y * v.y + v.z * v.z + v.w * v.w;
#pragma unroll
    for (int o = 16; o > 0; o >>= 1) s += __shfl_xor_sync(0xffffffffu, s, o);
    if (lane == 0) g_norm[warp] = s;
}

// ---------------------------------------------------------------------------
// 2) Attention tile: computes the att matrix ONCE per (i,j) tile and emits
//    BOTH marginals: per-i sums (-> x2_a partials, shfl over tx lanes) and
//    per-j sums (-> x1_a partials, smem cross-warp reduce).
//    att[b,i,j] = 1/(1+sqrt(|x2_i|^2+|x1_j|^2-2<x2_i,x1_j>+eps))
// ---------------------------------------------------------------------------
__global__ void __launch_bounds__(256) attn_tile(const float* __restrict__ x1,
                                                 const float* __restrict__ x2) {
    int it = blockIdx.x;            // i tile (x2 rows), 0..4
    int jt = blockIdx.y;            // j tile (x1 rows), 0..4
    int b  = blockIdx.z;            // 0..15

    const float* Ag = x2 + (size_t)b * N_ * H_;   // rows i
    const float* Bg = x1 + (size_t)b * N_ * H_;   // rows j
    const float* nA = g_norm + BN_ + b * N_;      // x2 norms
    const float* nB = g_norm + b * N_;            // x1 norms

    // Transposed tiles: [h within 64-chunk][row], stride 68 (16B aligned).
    __shared__ float As[64][68];
    __shared__ float Bs[64][68];

    int tid = threadIdx.x;
    int tx = tid & 15;              // j group
    int ty = tid >> 4;              // i group
    int i0 = it * 64;
    int j0 = jt * 64;

    float acc[4][4];                // [r over i][c over j]
#pragma unroll
    for (int r = 0; r < 4; r++)
#pragma unroll
        for (int c = 0; c < 4; c++) acc[r][c] = 0.0f;

    for (int hc = 0; hc < H_; hc += 64) {
        __syncthreads();
        int rot = tid & 3;
#pragma unroll
        for (int i = tid; i < 1024; i += 256) {
            int r  = i >> 4;
            int c4 = i & 15;
            float4 v = make_float4(0.f, 0.f, 0.f, 0.f);
            int row = i0 + r;
            if (row < N_)
                v = *reinterpret_cast<const float4*>(Ag + (size_t)row * H_ + hc + c4 * 4);
            float vv[4] = {v.x, v.y, v.z, v.w};
#pragma unroll
            for (int jj = 0; jj < 4; jj++) {
                int j = (jj + rot) & 3;
                As[c4 * 4 + j][r] = vv[j];
            }
        }
#pragma unroll
        for (int i = tid; i < 1024; i += 256) {
            int r  = i >> 4;
            int c4 = i & 15;
            float4 v = make_float4(0.f, 0.f, 0.f, 0.f);
            int row = j0 + r;
            if (row < N_)
                v = *reinterpret_cast<const float4*>(Bg + (size_t)row * H_ + hc + c4 * 4);
            float vv[4] = {v.x, v.y, v.z, v.w};
#pragma unroll
            for (int jj = 0; jj < 4; jj++) {
                int j = (jj + rot) & 3;
                Bs[c4 * 4 + j][r] = vv[j];
            }
        }
        __syncthreads();

#pragma unroll 16
        for (int h = 0; h < 64; h++) {
            float4 iv = *reinterpret_cast<const float4*>(&As[h][ty * 4]);
            float4 jv = *reinterpret_cast<const float4*>(&Bs[h][tx * 4]);
            acc[0][0] = fmaf(iv.x, jv.x, acc[0][0]);
            acc[0][1] = fmaf(iv.x, jv.y, acc[0][1]);
            acc[0][2] = fmaf(iv.x, jv.z, acc[0][2]);
            acc[0][3] = fmaf(iv.x, jv.w, acc[0][3]);
            acc[1][0] = fmaf(iv.y, jv.x, acc[1][0]);
            acc[1][1] = fmaf(iv.y, jv.y, acc[1][1]);
            acc[1][2] = fmaf(iv.y, jv.z, acc[1][2]);
            acc[1][3] = fmaf(iv.y, jv.w, acc[1][3]);
            acc[2][0] = fmaf(iv.z, jv.x, acc[2][0]);
            acc[2][1] = fmaf(iv.z, jv.y, acc[2][1]);
            acc[2][2] = fmaf(iv.z, jv.z, acc[2][2]);
            acc[2][3] = fmaf(iv.z, jv.w, acc[2][3]);
            acc[3][0] = fmaf(iv.w, jv.x, acc[3][0]);
            acc[3][1] = fmaf(iv.w, jv.y, acc[3][1]);
            acc[3][2] = fmaf(iv.w, jv.z, acc[3][2]);
            acc[3][3] = fmaf(iv.w, jv.w, acc[3][3]);
        }
    }

    // Epilogue: attention values + both marginals.
    float nb[4];
#pragma unroll
    for (int c = 0; c < 4; c++) {
        int j = j0 + tx * 4 + c;
        nb[c] = (j < N_) ? nB[j] : 0.0f;
    }
    float jp[4] = {0.f, 0.f, 0.f, 0.f};   // per-j (column) partials
#pragma unroll
    for (int r = 0; r < 4; r++) {
        int i = i0 + ty * 4 + r;
        float is = 0.0f;                   // per-i (row) partial
        if (i < N_) {
            float na = nA[i];
#pragma unroll
            for (int c = 0; c < 4; c++) {
                int j = j0 + tx * 4 + c;
                if (j < N_) {
                    float d2  = fmaxf(na + nb[c] - 2.0f * acc[r][c], 0.0f) + EPS_;
                    float att = att_of_d2(d2);
                    is += att;
                    jp[c] += att;
                }
            }
        }
#pragma unroll
        for (int o = 1; o < 16; o <<= 1) is += __shfl_xor_sync(0xffffffffu, is, o);
        if (tx == 0 && i < N_)
            g_p2[(b * 5 + jt) * 320 + i] = is;
    }

    // Cross-warp reduction for per-j sums (reuse As as a [16][64] buffer).
    __syncthreads();
    float* red = &As[0][0];
    *reinterpret_cast<float4*>(red + ty * 64 + tx * 4) =
        make_float4(jp[0], jp[1], jp[2], jp[3]);
    __syncthreads();
    if (tid < 64) {
        float s = 0.0f;
#pragma unroll
        for (int t = 0; t < 16; t++) s += red[t * 64 + tid];
        int j = j0 + tid;
        if (j < N_) g_p1[(b * 5 + it) * 320 + j] = s;
    }
}

// ---------------------------------------------------------------------------
// 3) Reduce the 5 tile partials per (side, b, q).
// ---------------------------------------------------------------------------
__global__ void reduce_partials_kernel() {
    int i = blockIdx.x * blockDim.x + threadIdx.x;
    if (i >= 2 * BN_) return;
    int s   = i / BN_;
    int rem = i - s * BN_;
    int b   = rem / N_;
    int q   = rem - b * N_;
    const float* p = (s == 0) ? g_p1 : g_p2;
    float sum = 0.0f;
#pragma unroll
    for (int t = 0; t < 5; t++) sum += p[(b * 5 + t) * 320 + q];
    g_asum[i] = sum;
}

// ---------------------------------------------------------------------------
// 4) Windowed weighted-sum epilogue (round-1 shape: 1 float4 out/thread,
//    1024 blocks — the fastest wp measured, 5.44us):
//    out_w[b,l,h] = sum_{k=0..3} x_w[b,l+k,h] * a_w[b,l+k]
// ---------------------------------------------------------------------------
__global__ void wp_kernel(const float* __restrict__ x1,
                          const float* __restrict__ x2,
                          float* __restrict__ out) {
    int i = blockIdx.x * blockDim.x + threadIdx.x;   // over (w,b,l,h4)
    if (i >= 2 * B_ * L_ * (H_ / 4)) return;
    int h4 = i & 31;
    int l  = (i >> 5) & 255;
    int b  = (i >> 13) & 15;
    int w  = i >> 17;
    const float* x = (w ? x2 : x1) + (size_t)b * N_ * H_;
    const float* a = g_asum + w * BN_ + b * N_;
    float4 o = make_float4(0.f, 0.f, 0.f, 0.f);
#pragma unroll
    for (int k = 0; k < W_; k++) {
        float4 v = *reinterpret_cast<const float4*>(x + (size_t)(l + k) * H_ + h4 * 4);
        float wg = a[l + k];
        o.x = fmaf(v.x, wg, o.x);
        o.y = fmaf(v.y, wg, o.y);
        o.z = fmaf(v.z, wg, o.z);
        o.w = fmaf(v.w, wg, o.w);
    }
    reinterpret_cast<float4*>(out)[i] = o;
}

// ---------------------------------------------------------------------------
extern "C" void kernel_launch(void* const* d_in, const int* in_sizes, int n_in,
                              void* d_out, int out_size) {
    const float* x1 = (const float*)d_in[0];
    const float* x2 = (const float*)d_in[1];
    float* out = (float*)d_out;

    norms_kernel<<<(2 * BN_ * 32 + 255) / 256, 256>>>(x1, x2);

    dim3 grid(5, 5, 16);
    attn_tile<<<grid, 256>>>(x1, x2);

    reduce_partials_kernel<<<(2 * BN_ + 255) / 256, 256>>>();

    wp_kernel<<<(2 * B_ * L_ * 32 + 255) / 256, 256>>>(x1, x2, out);
}

// round 7
// speedup vs baseline: 2.7569x; 1.3077x over previous
#include <cuda_runtime.h>

#define B_ 16
#define L_ 256
#define W_ 4
#define N_ 259          // L + W - 1
#define H_ 128
#define EPS_ 1e-6f
#define BN_ (B_ * N_)   // 4144

#define TS_ 96          // attention tile size
#define KC_ 32          // h-chunk
#define SSTR_ 98        // smem row stride (floats), 8B-aligned

// Scratch (no allocations allowed).
__device__ float g_norm[2 * BN_];        // [x1 rows | x2 rows]
__device__ float g_p1[16 * 3 * 320];     // x1_a partials: [b][it][j padded]
__device__ float g_p2[16 * 3 * 320];     // x2_a partials: [b][jt][i padded]
__device__ float g_asum[2 * BN_];        // [x1_a | x2_a]

// att = 1/(1+sqrt(d2)) = r/(1+r), r = rsqrt(d2). Exact identity, one MUFU.RSQ.
__device__ __forceinline__ float att_of_d2(float d2) {
    float r = rsqrtf(d2);
    return __fdividef(r, 1.0f + r);
}

// ---------------------------------------------------------------------------
// 1) Row norms: one warp per (tensor, b, n) row of 128 floats.
// ---------------------------------------------------------------------------
__global__ void norms_kernel(const float* __restrict__ x1,
                             const float* __restrict__ x2) {
    int gt   = blockIdx.x * blockDim.x + threadIdx.x;
    int warp = gt >> 5;
    int lane = gt & 31;
    if (warp >= 2 * BN_) return;
    const float* x = (warp < BN_) ? x1 : x2;
    int row = (warp < BN_) ? warp : warp - BN_;
    float4 v = reinterpret_cast<const float4*>(x + (size_t)row * H_)[lane];
    float s = v.x * v.x + v.y * v.y + v.z * v.z + v.w * v.w;
#pragma unroll
    for (int o = 16; o > 0; o >>= 1) s += __shfl_xor_sync(0xffffffffu, s, o);
    if (lane == 0) g_norm[warp] = s;
}

// ---------------------------------------------------------------------------
// 2) Attention tile 96x96, 6x6 register tile (FMA-bound: 36 FMA per 12 smem
//    floats per h). Computes att once per (i,j) and emits BOTH marginals.
//    Grid (3,3,16) = (it, jt, b).
// ---------------------------------------------------------------------------
__global__ void __launch_bounds__(256) attn_tile(const float* __restrict__ x1,
                                                 const float* __restrict__ x2) {
    int it = blockIdx.x;            // i tile (x2 rows), 0..2
    int jt = blockIdx.y;            // j tile (x1 rows), 0..2
    int b  = blockIdx.z;            // 0..15

    const float* Ag = x2 + (size_t)b * N_ * H_;   // rows i
    const float* Bg = x1 + (size_t)b * N_ * H_;   // rows j
    const float* nA = g_norm + BN_ + b * N_;      // x2 norms
    const float* nB = g_norm + b * N_;            // x1 norms

    // Transposed tiles: [h within chunk][row]
    __shared__ float As[KC_][SSTR_];
    __shared__ float Bs[KC_][SSTR_];

    int tid = threadIdx.x;
    int tx = tid & 15;              // j group (6 cols each)
    int ty = tid >> 4;              // i group (6 rows each)
    int i0 = it * TS_;
    int j0 = jt * TS_;

    float acc[6][6];
#pragma unroll
    for (int r = 0; r < 6; r++)
#pragma unroll
        for (int c = 0; c < 6; c++) acc[r][c] = 0.0f;

    for (int hc = 0; hc < H_; hc += KC_) {
        __syncthreads();
        // Stage: 96 rows x 8 float4 (32 floats) per operand, coalesced loads,
        // transpose scatter (scalar STS).
#pragma unroll
        for (int idx = tid; idx < 768; idx += 256) {
            int r  = idx >> 3;      // row in tile 0..95
            int c4 = idx & 7;       // float4 index along h-chunk
            float4 v = make_float4(0.f, 0.f, 0.f, 0.f);
            int row = i0 + r;
            if (row < N_)
                v = *reinterpret_cast<const float4*>(Ag + (size_t)row * H_ + hc + c4 * 4);
            As[c4 * 4 + 0][r] = v.x;
            As[c4 * 4 + 1][r] = v.y;
            As[c4 * 4 + 2][r] = v.z;
            As[c4 * 4 + 3][r] = v.w;
        }
#pragma unroll
        for (int idx = tid; idx < 768; idx += 256) {
            int r  = idx >> 3;
            int c4 = idx & 7;
            float4 v = make_float4(0.f, 0.f, 0.f, 0.f);
            int row = j0 + r;
            if (row < N_)
                v = *reinterpret_cast<const float4*>(Bg + (size_t)row * H_ + hc + c4 * 4);
            Bs[c4 * 4 + 0][r] = v.x;
            Bs[c4 * 4 + 1][r] = v.y;
            Bs[c4 * 4 + 2][r] = v.z;
            Bs[c4 * 4 + 3][r] = v.w;
        }
        __syncthreads();

#pragma unroll 8
        for (int h = 0; h < KC_; h++) {
            float av[6], bv[6];
            float2 t0 = *reinterpret_cast<const float2*>(&As[h][ty * 6 + 0]);
            float2 t1 = *reinterpret_cast<const float2*>(&As[h][ty * 6 + 2]);
            float2 t2 = *reinterpret_cast<const float2*>(&As[h][ty * 6 + 4]);
            av[0] = t0.x; av[1] = t0.y; av[2] = t1.x;
            av[3] = t1.y; av[4] = t2.x; av[5] = t2.y;
            float2 u0 = *reinterpret_cast<const float2*>(&Bs[h][tx * 6 + 0]);
            float2 u1 = *reinterpret_cast<const float2*>(&Bs[h][tx * 6 + 2]);
            float2 u2 = *reinterpret_cast<const float2*>(&Bs[h][tx * 6 + 4]);
            bv[0] = u0.x; bv[1] = u0.y; bv[2] = u1.x;
            bv[3] = u1.y; bv[4] = u2.x; bv[5] = u2.y;
#pragma unroll
            for (int r = 0; r < 6; r++)
#pragma unroll
                for (int c = 0; c < 6; c++)
                    acc[r][c] = fmaf(av[r], bv[c], acc[r][c]);
        }
    }

    // Epilogue: attention + both marginals (masked at boundaries).
    float nb[6];
    bool  jb[6];
#pragma unroll
    for (int c = 0; c < 6; c++) {
        int j = j0 + tx * 6 + c;
        jb[c] = (j < N_);
        nb[c] = jb[c] ? nB[j] : 0.0f;
    }
    float jp[6] = {0.f, 0.f, 0.f, 0.f, 0.f, 0.f};
#pragma unroll
    for (int r = 0; r < 6; r++) {
        int i = i0 + ty * 6 + r;
        float is = 0.0f;
        if (i < N_) {
            float na = nA[i];
#pragma unroll
            for (int c = 0; c < 6; c++) {
                if (jb[c]) {
                    float d2  = fmaxf(na + nb[c] - 2.0f * acc[r][c], 0.0f) + EPS_;
                    float att = att_of_d2(d2);
                    is += att;
                    jp[c] += att;
                }
            }
        }
        // reduce across the 16 tx lanes (stays within each 16-lane half)
#pragma unroll
        for (int o = 1; o < 16; o <<= 1)
            is += __shfl_xor_sync(0xffffffffu, is, o);
        if (tx == 0 && i < N_)
            g_p2[(b * 3 + jt) * 320 + i] = is;
    }

    // Cross-warp reduction for per-j (column) sums; reuse As ([16][96] layout).
    __syncthreads();
    float* red = &As[0][0];
#pragma unroll
    for (int c = 0; c < 6; c++)
        red[ty * 96 + tx * 6 + c] = jp[c];
    __syncthreads();
    if (tid < 96) {
        float s = 0.0f;
#pragma unroll
        for (int t = 0; t < 16; t++) s += red[t * 96 + tid];
        int j = j0 + tid;
        if (j < N_) g_p1[(b * 3 + it) * 320 + j] = s;
    }
}

// ---------------------------------------------------------------------------
// 3) Reduce the 3 tile partials per (side, b, q).
// ---------------------------------------------------------------------------
__global__ void reduce_partials_kernel() {
    int i = blockIdx.x * blockDim.x + threadIdx.x;
    if (i >= 2 * BN_) return;
    int s   = i / BN_;
    int rem = i - s * BN_;
    int b   = rem / N_;
    int q   = rem - b * N_;
    const float* p = (s == 0) ? g_p1 : g_p2;
    float sum = 0.0f;
#pragma unroll
    for (int t = 0; t < 3; t++) sum += p[(b * 3 + t) * 320 + q];
    g_asum[i] = sum;
}

// ---------------------------------------------------------------------------
// 4) Windowed weighted-sum epilogue (measured-best shape: 1 float4/thread).
// ---------------------------------------------------------------------------
__global__ void wp_kernel(const float* __restrict__ x1,
                          const float* __restrict__ x2,
                          float* __restrict__ out) {
    int i = blockIdx.x * blockDim.x + threadIdx.x;   // over (w,b,l,h4)
    if (i >= 2 * B_ * L_ * (H_ / 4)) return;
    int h4 = i & 31;
    int l  = (i >> 5) & 255;
    int b  = (i >> 13) & 15;
    int w  = i >> 17;
    const float* x = (w ? x2 : x1) + (size_t)b * N_ * H_;
    const float* a = g_asum + w * BN_ + b * N_;
    float4 o = make_float4(0.f, 0.f, 0.f, 0.f);
#pragma unroll
    for (int k = 0; k < W_; k++) {
        float4 v = *reinterpret_cast<const float4*>(x + (size_t)(l + k) * H_ + h4 * 4);
        float wg = a[l + k];
        o.x = fmaf(v.x, wg, o.x);
        o.y = fmaf(v.y, wg, o.y);
        o.z = fmaf(v.z, wg, o.z);
        o.w = fmaf(v.w, wg, o.w);
    }
    reinterpret_cast<float4*>(out)[i] = o;
}

// ---------------------------------------------------------------------------
extern "C" void kernel_launch(void* const* d_in, const int* in_sizes, int n_in,
                              void* d_out, int out_size) {
    const float* x1 = (const float*)d_in[0];
    const float* x2 = (const float*)d_in[1];
    float* out = (float*)d_out;

    norms_kernel<<<(2 * BN_ * 32 + 255) / 256, 256>>>(x1, x2);

    dim3 grid(3, 3, 16);
    attn_tile<<<grid, 256>>>(x1, x2);

    reduce_partials_kernel<<<(2 * BN_ + 255) / 256, 256>>>();

    wp_kernel<<<(2 * B_ * L_ * 32 + 255) / 256, 256>>>(x1, x2, out);
}

// round 8
// speedup vs baseline: 2.7607x; 1.0014x over previous
#include <cuda_runtime.h>

#define B_ 16
#define L_ 256
#define W_ 4
#define N_ 259          // L + W - 1
#define H_ 128
#define EPS_ 1e-6f
#define BN_ (B_ * N_)   // 4144

#define TS_ 96          // attention tile size
#define KC_ 32          // h-chunk
#define SSTR_ 98        // smem row stride (floats), 8B-aligned

// Scratch (no allocations allowed).
__device__ float g_p1[16 * 3 * 320];     // x1_a partials: [b][it][j padded]
__device__ float g_p2[16 * 3 * 320];     // x2_a partials: [b][jt][i padded]

// att = 1/(1+sqrt(d2)) = r/(1+r), r = rsqrt(d2). Exact identity, one MUFU.RSQ.
__device__ __forceinline__ float att_of_d2(float d2) {
    float r = rsqrtf(d2);
    return __fdividef(r, 1.0f + r);
}

// ---------------------------------------------------------------------------
// 1) Attention tile 96x96, 6x6 register tile. Row norms are computed inline
//    during staging (per-thread partials -> 8-lane shfl -> smem), so there is
//    no separate norms kernel. Emits BOTH marginals. Grid (3,3,16)=(it,jt,b).
// ---------------------------------------------------------------------------
__global__ void __launch_bounds__(256) attn_tile(const float* __restrict__ x1,
                                                 const float* __restrict__ x2) {
    int it = blockIdx.x;            // i tile (x2 rows), 0..2
    int jt = blockIdx.y;            // j tile (x1 rows), 0..2
    int b  = blockIdx.z;            // 0..15

    const float* Ag = x2 + (size_t)b * N_ * H_;   // rows i
    const float* Bg = x1 + (size_t)b * N_ * H_;   // rows j

    // Transposed tiles: [h within chunk][row]
    __shared__ float As[KC_][SSTR_];
    __shared__ float Bs[KC_][SSTR_];
    __shared__ float nAs[TS_];      // |x2_i|^2 for this block's i rows
    __shared__ float nBs[TS_];      // |x1_j|^2 for this block's j rows

    int tid = threadIdx.x;
    int tx = tid & 15;              // j group (6 cols each)
    int ty = tid >> 4;              // i group (6 rows each)
    int i0 = it * TS_;
    int j0 = jt * TS_;

    float acc[6][6];
#pragma unroll
    for (int r = 0; r < 6; r++)
#pragma unroll
        for (int c = 0; c < 6; c++) acc[r][c] = 0.0f;

    // Per-thread norm partials: iteration k stages row (tid>>3)+32k at
    // float4-chunk c4 = tid&7; accumulate v.v across the 4 h-chunks.
    float napar[3] = {0.f, 0.f, 0.f};
    float nbpar[3] = {0.f, 0.f, 0.f};

    for (int hc = 0; hc < H_; hc += KC_) {
        __syncthreads();
#pragma unroll
        for (int k = 0; k < 3; k++) {
            int idx = tid + k * 256;
            int r  = idx >> 3;      // row in tile 0..95
            int c4 = idx & 7;       // float4 index along h-chunk
            float4 v = make_float4(0.f, 0.f, 0.f, 0.f);
            int row = i0 + r;
            if (row < N_)
                v = *reinterpret_cast<const float4*>(Ag + (size_t)row * H_ + hc + c4 * 4);
            napar[k] += v.x * v.x + v.y * v.y + v.z * v.z + v.w * v.w;
            As[c4 * 4 + 0][r] = v.x;
            As[c4 * 4 + 1][r] = v.y;
            As[c4 * 4 + 2][r] = v.z;
            As[c4 * 4 + 3][r] = v.w;
        }
#pragma unroll
        for (int k = 0; k < 3; k++) {
            int idx = tid + k * 256;
            int r  = idx >> 3;
            int c4 = idx & 7;
            float4 v = make_float4(0.f, 0.f, 0.f, 0.f);
            int row = j0 + r;
            if (row < N_)
                v = *reinterpret_cast<const float4*>(Bg + (size_t)row * H_ + hc + c4 * 4);
            nbpar[k] += v.x * v.x + v.y * v.y + v.z * v.z + v.w * v.w;
            Bs[c4 * 4 + 0][r] = v.x;
            Bs[c4 * 4 + 1][r] = v.y;
            Bs[c4 * 4 + 2][r] = v.z;
            Bs[c4 * 4 + 3][r] = v.w;
        }
        __syncthreads();

#pragma unroll 8
        for (int h = 0; h < KC_; h++) {
            float av[6], bv[6];
            float2 t0 = *reinterpret_cast<const float2*>(&As[h][ty * 6 + 0]);
            float2 t1 = *reinterpret_cast<const float2*>(&As[h][ty * 6 + 2]);
            float2 t2 = *reinterpret_cast<const float2*>(&As[h][ty * 6 + 4]);
            av[0] = t0.x; av[1] = t0.y; av[2] = t1.x;
            av[3] = t1.y; av[4] = t2.x; av[5] = t2.y;
            float2 u0 = *reinterpret_cast<const float2*>(&Bs[h][tx * 6 + 0]);
            float2 u1 = *reinterpret_cast<const float2*>(&Bs[h][tx * 6 + 2]);
            float2 u2 = *reinterpret_cast<const float2*>(&Bs[h][tx * 6 + 4]);
            bv[0] = u0.x; bv[1] = u0.y; bv[2] = u1.x;
            bv[3] = u1.y; bv[4] = u2.x; bv[5] = u2.y;
#pragma unroll
            for (int r = 0; r < 6; r++)
#pragma unroll
                for (int c = 0; c < 6; c++)
                    acc[r][c] = fmaf(av[r], bv[c], acc[r][c]);
        }
    }

    // Finish norms: reduce across the 8 lanes sharing each row (lane groups
    // are 8-aligned within a warp), then publish to smem.
#pragma unroll
    for (int o = 1; o < 8; o <<= 1) {
#pragma unroll
        for (int k = 0; k < 3; k++) {
            napar[k] += __shfl_xor_sync(0xffffffffu, napar[k], o);
            nbpar[k] += __shfl_xor_sync(0xffffffffu, nbpar[k], o);
        }
    }
    if ((tid & 7) == 0) {
        int r0 = tid >> 3;
#pragma unroll
        for (int k = 0; k < 3; k++) {
            nAs[r0 + 32 * k] = napar[k];
            nBs[r0 + 32 * k] = nbpar[k];
        }
    }
    __syncthreads();

    // Epilogue: attention + both marginals (masked at boundaries).
    float nb[6];
    bool  jb[6];
#pragma unroll
    for (int c = 0; c < 6; c++) {
        int j = j0 + tx * 6 + c;
        jb[c] = (j < N_);
        nb[c] = nBs[tx * 6 + c];
    }
    float jp[6] = {0.f, 0.f, 0.f, 0.f, 0.f, 0.f};
#pragma unroll
    for (int r = 0; r < 6; r++) {
        int i = i0 + ty * 6 + r;
        float is = 0.0f;
        if (i < N_) {
            float na = nAs[ty * 6 + r];
#pragma unroll
            for (int c = 0; c < 6; c++) {
                if (jb[c]) {
                    float d2  = fmaxf(na + nb[c] - 2.0f * acc[r][c], 0.0f) + EPS_;
                    float att = att_of_d2(d2);
                    is += att;
                    jp[c] += att;
                }
            }
        }
        // reduce across the 16 tx lanes (stays within each 16-lane half)
#pragma unroll
        for (int o = 1; o < 16; o <<= 1)
            is += __shfl_xor_sync(0xffffffffu, is, o);
        if (tx == 0 && i < N_)
            g_p2[(b * 3 + jt) * 320 + i] = is;
    }

    // Cross-warp reduction for per-j (column) sums; reuse As ([16][96] layout).
    __syncthreads();
    float* red = &As[0][0];
#pragma unroll
    for (int c = 0; c < 6; c++)
        red[ty * 96 + tx * 6 + c] = jp[c];
    __syncthreads();
    if (tid < 96) {
        float s = 0.0f;
#pragma unroll
        for (int t = 0; t < 16; t++) s += red[t * 96 + tid];
        int j = j0 + tid;
        if (j < N_) g_p1[(b * 3 + it) * 320 + j] = s;
    }
}

// ---------------------------------------------------------------------------
// 2) Windowed weighted-sum epilogue with the 3-slot partial reduction fused:
//    block = (w, b, 8 consecutive l); 11 threads stage the block's a-window
//    into smem (33 loads/block), then the measured-best wp body runs on it.
// ---------------------------------------------------------------------------
__global__ void __launch_bounds__(256) wp_kernel(const float* __restrict__ x1,
                                                 const float* __restrict__ x2,
                                                 float* __restrict__ out) {
    __shared__ float sa[12];
    int bi   = blockIdx.x;          // 0..1023
    int lblk = bi & 31;
    int b    = (bi >> 5) & 15;
    int w    = bi >> 9;
    int tid  = threadIdx.x;
    int l0   = lblk * 8;

    if (tid < 11) {
        const float* p = (w ? g_p2 : g_p1) + b * 3 * 320;
        int q = l0 + tid;           // max 248+10 = 258 < N_
        sa[tid] = p[q] + p[320 + q] + p[640 + q];
    }
    __syncthreads();

    int h4 = tid & 31;
    int dl = tid >> 5;
    int l  = l0 + dl;
    const float* x = (w ? x2 : x1) + (size_t)b * N_ * H_ + h4 * 4;

    float4 o = make_float4(0.f, 0.f, 0.f, 0.f);
#pragma unroll
    for (int k = 0; k < W_; k++) {
        float4 v = *reinterpret_cast<const float4*>(x + (size_t)(l + k) * H_);
        float wg = sa[dl + k];
        o.x = fmaf(v.x, wg, o.x);
        o.y = fmaf(v.y, wg, o.y);
        o.z = fmaf(v.z, wg, o.z);
        o.w = fmaf(v.w, wg, o.w);
    }
    size_t oi = ((size_t)(w * 16 + b) * 256 + l) * 32 + h4;
    reinterpret_cast<float4*>(out)[oi] = o;
}

// ---------------------------------------------------------------------------
extern "C" void kernel_launch(void* const* d_in, const int* in_sizes, int n_in,
                              void* d_out, int out_size) {
    const float* x1 = (const float*)d_in[0];
    const float* x2 = (const float*)d_in[1];
    float* out = (float*)d_out;

    dim3 grid(3, 3, 16);
    attn_tile<<<grid, 256>>>(x1, x2);

    wp_kernel<<<1024, 256>>>(x1, x2, out);
}

// round 9
// speedup vs baseline: 3.0226x; 1.0949x over previous
#include <cuda_runtime.h>

#define B_ 16
#define L_ 256
#define W_ 4
#define N_ 259          // L + W - 1
#define H_ 128
#define EPS_ 1e-6f
#define BN_ (B_ * N_)   // 4144

#define TS_ 96          // attention tile size
#define KC_ 32          // h-chunk
#define SSTR_ 98        // smem row stride (floats), 8B-aligned

// Scratch (no allocations allowed).
__device__ float g_p1[16 * 3 * 320];     // x1_a partials: [b][it][j padded]
__device__ float g_p2[16 * 3 * 320];     // x2_a partials: [b][jt][i padded]

// att = 1/(1+sqrt(d2)) = r/(1+r), r = rsqrt(d2). Exact identity, one MUFU.RSQ.
__device__ __forceinline__ float att_of_d2(float d2) {
    float r = rsqrtf(d2);
    return __fdividef(r, 1.0f + r);
}

// ---------------------------------------------------------------------------
// 1) Attention tile 96x96, 6x6 register tile, SOFTWARE-PIPELINED staging:
//    the next h-chunk is prefetched into registers before the compute phase,
//    so global-load latency is hidden behind the 1152-FFMA inner loop.
//    Row norms computed inline during staging. Grid (3,3,16)=(it,jt,b).
// ---------------------------------------------------------------------------
__global__ void __launch_bounds__(256) attn_tile(const float* __restrict__ x1,
                                                 const float* __restrict__ x2) {
    int it = blockIdx.x;            // i tile (x2 rows), 0..2
    int jt = blockIdx.y;            // j tile (x1 rows), 0..2
    int b  = blockIdx.z;            // 0..15

    const float* Ag = x2 + (size_t)b * N_ * H_;   // rows i
    const float* Bg = x1 + (size_t)b * N_ * H_;   // rows j

    // Transposed tiles: [h within chunk][row]
    __shared__ float As[KC_][SSTR_];
    __shared__ float Bs[KC_][SSTR_];
    __shared__ float nAs[TS_];      // |x2_i|^2 for this block's i rows
    __shared__ float nBs[TS_];      // |x1_j|^2 for this block's j rows

    int tid = threadIdx.x;
    int tx = tid & 15;              // j group (6 cols each)
    int ty = tid >> 4;              // i group (6 rows each)
    int i0 = it * TS_;
    int j0 = jt * TS_;

    // Staging geometry: c4 = tid&7 is chunk-invariant; row r = rbase + 32k.
    int c4    = tid & 7;
    int rbase = tid >> 3;           // 0..31

    // Validity + base pointers per k (row fixed across chunks).
    bool av[3], bv3[3];
    const float4* ap[3];
    const float4* bp[3];
#pragma unroll
    for (int k = 0; k < 3; k++) {
        int ra = i0 + rbase + 32 * k;
        int rb = j0 + rbase + 32 * k;
        av[k]  = (ra < N_);
        bv3[k] = (rb < N_);
        ap[k] = reinterpret_cast<const float4*>(Ag + (size_t)ra * H_ + c4 * 4);
        bp[k] = reinterpret_cast<const float4*>(Bg + (size_t)rb * H_ + c4 * 4);
    }

    float acc[6][6];
#pragma unroll
    for (int r = 0; r < 6; r++)
#pragma unroll
        for (int c = 0; c < 6; c++) acc[r][c] = 0.0f;

    float napar[3] = {0.f, 0.f, 0.f};
    float nbpar[3] = {0.f, 0.f, 0.f};

    float4 pA[3], pB[3];
    const float4 z4 = make_float4(0.f, 0.f, 0.f, 0.f);
    // Prefetch chunk 0.
#pragma unroll
    for (int k = 0; k < 3; k++) {
        pA[k] = av[k]  ? ap[k][0] : z4;
        pB[k] = bv3[k] ? bp[k][0] : z4;
    }

    for (int chunk = 0; chunk < 4; chunk++) {
        __syncthreads();            // previous compute finished reading smem
        // Commit prefetched registers to smem (+ norm partials).
#pragma unroll
        for (int k = 0; k < 3; k++) {
            int r = rbase + 32 * k;
            float4 v = pA[k];
            napar[k] += v.x * v.x + v.y * v.y + v.z * v.z + v.w * v.w;
            As[c4 * 4 + 0][r] = v.x;
            As[c4 * 4 + 1][r] = v.y;
            As[c4 * 4 + 2][r] = v.z;
            As[c4 * 4 + 3][r] = v.w;
            v = pB[k];
            nbpar[k] += v.x * v.x + v.y * v.y + v.z * v.z + v.w * v.w;
            Bs[c4 * 4 + 0][r] = v.x;
            Bs[c4 * 4 + 1][r] = v.y;
            Bs[c4 * 4 + 2][r] = v.z;
            Bs[c4 * 4 + 3][r] = v.w;
        }
        __syncthreads();
        // Issue next chunk's global loads; latency hidden by the FMA loop.
        if (chunk < 3) {
            int o4 = (chunk + 1) * (KC_ / 4);   // offset in float4s
#pragma unroll
            for (int k = 0; k < 3; k++) {
                pA[k] = av[k]  ? ap[k][o4] : z4;
                pB[k] = bv3[k] ? bp[k][o4] : z4;
            }
        }

#pragma unroll 8
        for (int h = 0; h < KC_; h++) {
            float avr[6], bvr[6];
            float2 t0 = *reinterpret_cast<const float2*>(&As[h][ty * 6 + 0]);
            float2 t1 = *reinterpret_cast<const float2*>(&As[h][ty * 6 + 2]);
            float2 t2 = *reinterpret_cast<const float2*>(&As[h][ty * 6 + 4]);
            avr[0] = t0.x; avr[1] = t0.y; avr[2] = t1.x;
            avr[3] = t1.y; avr[4] = t2.x; avr[5] = t2.y;
            float2 u0 = *reinterpret_cast<const float2*>(&Bs[h][tx * 6 + 0]);
            float2 u1 = *reinterpret_cast<const float2*>(&Bs[h][tx * 6 + 2]);
            float2 u2 = *reinterpret_cast<const float2*>(&Bs[h][tx * 6 + 4]);
            bvr[0] = u0.x; bvr[1] = u0.y; bvr[2] = u1.x;
            bvr[3] = u1.y; bvr[4] = u2.x; bvr[5] = u2.y;
#pragma unroll
            for (int r = 0; r < 6; r++)
#pragma unroll
                for (int c = 0; c < 6; c++)
                    acc[r][c] = fmaf(avr[r], bvr[c], acc[r][c]);
        }
    }

    // Finish norms: reduce across the 8 lanes sharing each row.
#pragma unroll
    for (int o = 1; o < 8; o <<= 1) {
#pragma unroll
        for (int k = 0; k < 3; k++) {
            napar[k] += __shfl_xor_sync(0xffffffffu, napar[k], o);
            nbpar[k] += __shfl_xor_sync(0xffffffffu, nbpar[k], o);
        }
    }
    if ((tid & 7) == 0) {
#pragma unroll
        for (int k = 0; k < 3; k++) {
            nAs[rbase + 32 * k] = napar[k];
            nBs[rbase + 32 * k] = nbpar[k];
        }
    }
    __syncthreads();

    // Epilogue: attention + both marginals (masked at boundaries).
    float nb[6];
    bool  jb[6];
#pragma unroll
    for (int c = 0; c < 6; c++) {
        int j = j0 + tx * 6 + c;
        jb[c] = (j < N_);
        nb[c] = nBs[tx * 6 + c];
    }
    float jp[6] = {0.f, 0.f, 0.f, 0.f, 0.f, 0.f};
#pragma unroll
    for (int r = 0; r < 6; r++) {
        int i = i0 + ty * 6 + r;
        float is = 0.0f;
        if (i < N_) {
            float na = nAs[ty * 6 + r];
#pragma unroll
            for (int c = 0; c < 6; c++) {
                if (jb[c]) {
                    float d2  = fmaxf(na + nb[c] - 2.0f * acc[r][c], 0.0f) + EPS_;
                    float att = att_of_d2(d2);
                    is += att;
                    jp[c] += att;
                }
            }
        }
#pragma unroll
        for (int o = 1; o < 16; o <<= 1)
            is += __shfl_xor_sync(0xffffffffu, is, o);
        if (tx == 0 && i < N_)
            g_p2[(b * 3 + jt) * 320 + i] = is;
    }

    // Cross-warp reduction for per-j (column) sums; reuse As ([16][96] layout).
    __syncthreads();
    float* red = &As[0][0];
#pragma unroll
    for (int c = 0; c < 6; c++)
        red[ty * 96 + tx * 6 + c] = jp[c];
    __syncthreads();
    if (tid < 96) {
        float s = 0.0f;
#pragma unroll
        for (int t = 0; t < 16; t++) s += red[t * 96 + tid];
        int j = j0 + tid;
        if (j < N_) g_p1[(b * 3 + it) * 320 + j] = s;
    }
}

// ---------------------------------------------------------------------------
// 2) Windowed weighted-sum epilogue with the 3-slot partial reduction fused:
//    block = (w, b, 8 consecutive l); 11 threads stage the block's a-window
//    into smem, then the measured-best wp body runs on it.
// ---------------------------------------------------------------------------
__global__ void __launch_bounds__(256) wp_kernel(const float* __restrict__ x1,
                                                 const float* __restrict__ x2,
                                                 float* __restrict__ out) {
    __shared__ float sa[12];
    int bi   = blockIdx.x;          // 0..1023
    int lblk = bi & 31;
    int b    = (bi >> 5) & 15;
    int w    = bi >> 9;
    int tid  = threadIdx.x;
    int l0   = lblk * 8;

    if (tid < 11) {
        const float* p = (w ? g_p2 : g_p1) + b * 3 * 320;
        int q = l0 + tid;           // max 248+10 = 258 < N_
        sa[tid] = p[q] + p[320 + q] + p[640 + q];
    }
    __syncthreads();

    int h4 = tid & 31;
    int dl = tid >> 5;
    int l  = l0 + dl;
    const float* x = (w ? x2 : x1) + (size_t)b * N_ * H_ + h4 * 4;

    float4 o = make_float4(0.f, 0.f, 0.f, 0.f);
#pragma unroll
    for (int k = 0; k < W_; k++) {
        float4 v = *reinterpret_cast<const float4*>(x + (size_t)(l + k) * H_);
        float wg = sa[dl + k];
        o.x = fmaf(v.x, wg, o.x);
        o.y = fmaf(v.y, wg, o.y);
        o.z = fmaf(v.z, wg, o.z);
        o.w = fmaf(v.w, wg, o.w);
    }
    size_t oi = ((size_t)(w * 16 + b) * 256 + l) * 32 + h4;
    reinterpret_cast<float4*>(out)[oi] = o;
}

// ---------------------------------------------------------------------------
extern "C" void kernel_launch(void* const* d_in, const int* in_sizes, int n_in,
                              void* d_out, int out_size) {
    const float* x1 = (const float*)d_in[0];
    const float* x2 = (const float*)d_in[1];
    float* out = (float*)d_out;

    dim3 grid(3, 3, 16);
    attn_tile<<<grid, 256>>>(x1, x2);

    wp_kernel<<<1024, 256>>>(x1, x2, out);
}

// round 10
// speedup vs baseline: 3.3506x; 1.1085x over previous
#include <cuda_runtime.h>
#include <cstdint>

#define B_ 16
#define L_ 256
#define W_ 4
#define N_ 259          // L + W - 1
#define H_ 128
#define EPS_ 1e-6f
#define BN_ (B_ * N_)   // 4144

#define TS_ 96          // attention tile size
#define KC_ 32          // h-chunk (16 f32x2 pairs)
#define HP_ 16          // h-pairs per chunk
#define SSTR2_ 98       // smem row stride in float2 (word stride 196 -> 2-wf floor)

// Scratch (no allocations allowed).
__device__ float g_p1[16 * 3 * 320];     // x1_a partials: [b][it][j padded]
__device__ float g_p2[16 * 3 * 320];     // x2_a partials: [b][jt][i padded]

// att = 1/(1+sqrt(d2)) = r/(1+r), r = rsqrt(d2). Exact identity, one MUFU.RSQ.
__device__ __forceinline__ float att_of_d2(float d2) {
    float r = rsqrtf(d2);
    return __fdividef(r, 1.0f + r);
}

// ---------------------------------------------------------------------------
// 1) Attention tile 96x96, 6x6 register tile, packed f32x2 FMA inner loop
//    (2 h-positions per instruction -> half the FMA instruction count).
//    Smem layout: [h-pair][row] of float2 = (x[2h2], x[2h2+1]).
//    Pipelined staging + inline norms as in round 9. Grid (3,3,16)=(it,jt,b).
// ---------------------------------------------------------------------------
__global__ void __launch_bounds__(256) attn_tile(const float* __restrict__ x1,
                                                 const float* __restrict__ x2) {
    int it = blockIdx.x;            // i tile (x2 rows), 0..2
    int jt = blockIdx.y;            // j tile (x1 rows), 0..2
    int b  = blockIdx.z;            // 0..15

    const float* Ag = x2 + (size_t)b * N_ * H_;   // rows i
    const float* Bg = x1 + (size_t)b * N_ * H_;   // rows j

    // One contiguous buffer: S2[0]=A operand, S2[1]=B operand.
    __shared__ float2 S2[2][HP_][SSTR2_];
    __shared__ float nAs[TS_];      // |x2_i|^2 for this block's i rows
    __shared__ float nBs[TS_];      // |x1_j|^2 for this block's j rows

    int tid = threadIdx.x;
    int tx = tid & 15;              // j group (6 cols each)
    int ty = tid >> 4;              // i group (6 rows each)
    int i0 = it * TS_;
    int j0 = jt * TS_;

    // Staging geometry: c4 = tid&7 (chunk-invariant float4 slot), r = rbase+32k.
    int c4    = tid & 7;
    int rbase = tid >> 3;           // 0..31

    bool av[3], bv3[3];
    const float4* ap[3];
    const float4* bp[3];
#pragma unroll
    for (int k = 0; k < 3; k++) {
        int ra = i0 + rbase + 32 * k;
        int rb = j0 + rbase + 32 * k;
        av[k]  = (ra < N_);
        bv3[k] = (rb < N_);
        ap[k] = reinterpret_cast<const float4*>(Ag + (size_t)ra * H_ + c4 * 4);
        bp[k] = reinterpret_cast<const float4*>(Bg + (size_t)rb * H_ + c4 * 4);
    }

    // Packed accumulators: acc2[r][c] = (sum over even h, sum over odd h).
    unsigned long long acc2[6][6];
#pragma unroll
    for (int r = 0; r < 6; r++)
#pragma unroll
        for (int c = 0; c < 6; c++) acc2[r][c] = 0ull;

    float napar[3] = {0.f, 0.f, 0.f};
    float nbpar[3] = {0.f, 0.f, 0.f};

    float4 pA[3], pB[3];
    const float4 z4 = make_float4(0.f, 0.f, 0.f, 0.f);
#pragma unroll
    for (int k = 0; k < 3; k++) {
        pA[k] = av[k]  ? ap[k][0] : z4;
        pB[k] = bv3[k] ? bp[k][0] : z4;
    }

    for (int chunk = 0; chunk < 4; chunk++) {
        __syncthreads();            // previous compute finished reading smem
        // Commit prefetched float4s as two float2 h-pairs each (+ norms).
#pragma unroll
        for (int k = 0; k < 3; k++) {
            int r = rbase + 32 * k;
            float4 v = pA[k];
            napar[k] += v.x * v.x + v.y * v.y + v.z * v.z + v.w * v.w;
            S2[0][c4 * 2 + 0][r] = make_float2(v.x, v.y);
            S2[0][c4 * 2 + 1][r] = make_float2(v.z, v.w);
            v = pB[k];
            nbpar[k] += v.x * v.x + v.y * v.y + v.z * v.z + v.w * v.w;
            S2[1][c4 * 2 + 0][r] = make_float2(v.x, v.y);
            S2[1][c4 * 2 + 1][r] = make_float2(v.z, v.w);
        }
        __syncthreads();
        // Issue next chunk's global loads; latency hidden by the FMA loop.
        if (chunk < 3) {
            int o4 = (chunk + 1) * (KC_ / 4);
#pragma unroll
            for (int k = 0; k < 3; k++) {
                pA[k] = av[k]  ? ap[k][o4] : z4;
                pB[k] = bv3[k] ? bp[k][o4] : z4;
            }
        }

#pragma unroll 4
        for (int h2 = 0; h2 < HP_; h2++) {
            unsigned long long a2[6], b2[6];
#pragma unroll
            for (int r = 0; r < 6; r++)
                a2[r] = *reinterpret_cast<const unsigned long long*>(
                    &S2[0][h2][ty * 6 + r]);
#pragma unroll
            for (int c = 0; c < 6; c++)
                b2[c] = *reinterpret_cast<const unsigned long long*>(
                    &S2[1][h2][tx * 6 + c]);
#pragma unroll
            for (int r = 0; r < 6; r++)
#pragma unroll
                for (int c = 0; c < 6; c++)
                    asm("fma.rn.f32x2 %0, %1, %2, %0;"
                        : "+l"(acc2[r][c]) : "l"(a2[r]), "l"(b2[c]));
        }
    }

    // Finish norms: reduce across the 8 lanes sharing each row.
#pragma unroll
    for (int o = 1; o < 8; o <<= 1) {
#pragma unroll
        for (int k = 0; k < 3; k++) {
            napar[k] += __shfl_xor_sync(0xffffffffu, napar[k], o);
            nbpar[k] += __shfl_xor_sync(0xffffffffu, nbpar[k], o);
        }
    }
    if ((tid & 7) == 0) {
#pragma unroll
        for (int k = 0; k < 3; k++) {
            nAs[rbase + 32 * k] = napar[k];
            nBs[rbase + 32 * k] = nbpar[k];
        }
    }
    __syncthreads();

    // Epilogue: unpack packed accumulators, attention + both marginals.
    float nb[6];
    bool  jb[6];
#pragma unroll
    for (int c = 0; c < 6; c++) {
        int j = j0 + tx * 6 + c;
        jb[c] = (j < N_);
        nb[c] = nBs[tx * 6 + c];
    }
    float jp[6] = {0.f, 0.f, 0.f, 0.f, 0.f, 0.f};
#pragma unroll
    for (int r = 0; r < 6; r++) {
        int i = i0 + ty * 6 + r;
        float is = 0.0f;
        if (i < N_) {
            float na = nAs[ty * 6 + r];
#pragma unroll
            for (int c = 0; c < 6; c++) {
                if (jb[c]) {
                    uint2 u = *reinterpret_cast<uint2*>(&acc2[r][c]);
                    float dot = __uint_as_float(u.x) + __uint_as_float(u.y);
                    float d2  = fmaxf(na + nb[c] - 2.0f * dot, 0.0f) + EPS_;
                    float att = att_of_d2(d2);
                    is += att;
                    jp[c] += att;
                }
            }
        }
#pragma unroll
        for (int o = 1; o < 16; o <<= 1)
            is += __shfl_xor_sync(0xffffffffu, is, o);
        if (tx == 0 && i < N_)
            g_p2[(b * 3 + jt) * 320 + i] = is;
    }

    // Cross-warp reduction for per-j (column) sums; reuse S2 as float buffer
    // (needs 16*96 = 6144 floats; S2 holds 2*16*98*2 = 6272 floats).
    __syncthreads();
    float* red = reinterpret_cast<float*>(S2);
#pragma unroll
    for (int c = 0; c < 6; c++)
        red[ty * 96 + tx * 6 + c] = jp[c];
    __syncthreads();
    if (tid < 96) {
        float s = 0.0f;
#pragma unroll
        for (int t = 0; t < 16; t++) s += red[t * 96 + tid];
        int j = j0 + tid;
        if (j < N_) g_p1[(b * 3 + it) * 320 + j] = s;
    }
}

// ---------------------------------------------------------------------------
// 2) Windowed weighted-sum epilogue with the 3-slot partial reduction fused
//    (unchanged from round 9 — measured stable).
// ---------------------------------------------------------------------------
__global__ void __launch_bounds__(256) wp_kernel(const float* __restrict__ x1,
                                                 const float* __restrict__ x2,
                                                 float* __restrict__ out) {
    __shared__ float sa[12];
    int bi   = blockIdx.x;          // 0..1023
    int lblk = bi & 31;
    int b    = (bi >> 5) & 15;
    int w    = bi >> 9;
    int tid  = threadIdx.x;
    int l0   = lblk * 8;

    if (tid < 11) {
        const float* p = (w ? g_p2 : g_p1) + b * 3 * 320;
        int q = l0 + tid;           // max 248+10 = 258 < N_
        sa[tid] = p[q] + p[320 + q] + p[640 + q];
    }
    __syncthreads();

    int h4 = tid & 31;
    int dl = tid >> 5;
    int l  = l0 + dl;
    const float* x = (w ? x2 : x1) + (size_t)b * N_ * H_ + h4 * 4;

    float4 o = make_float4(0.f, 0.f, 0.f, 0.f);
#pragma unroll
    for (int k = 0; k < W_; k++) {
        float4 v = *reinterpret_cast<const float4*>(x + (size_t)(l + k) * H_);
        float wg = sa[dl + k];
        o.x = fmaf(v.x, wg, o.x);
        o.y = fmaf(v.y, wg, o.y);
        o.z = fmaf(v.z, wg, o.z);
        o.w = fmaf(v.w, wg, o.w);
    }
    size_t oi = ((size_t)(w * 16 + b) * 256 + l) * 32 + h4;
    reinterpret_cast<float4*>(out)[oi] = o;
}

// ---------------------------------------------------------------------------
extern "C" void kernel_launch(void* const* d_in, const int* in_sizes, int n_in,
                              void* d_out, int out_size) {
    const float* x1 = (const float*)d_in[0];
    const float* x2 = (const float*)d_in[1];
    float* out = (float*)d_out;

    dim3 grid(3, 3, 16);
    attn_tile<<<grid, 256>>>(x1, x2);

    wp_kernel<<<1024, 256>>>(x1, x2, out);
}